// round 9
// baseline (speedup 1.0000x reference)
#include <cuda_runtime.h>
#include <cstdint>
#include <cstddef>

namespace {
constexpr int kB = 16, kS = 2048, kD = 128, TQ = 64, TK = 64, NT = 256;
constexpr int NKT = kS / TK;   // 32
constexpr int QP = 132;        // Q pitch  (A-frag LDS conflict-free)
constexpr int KPITCH = 132;    // K pitch  (QK B-frag conflict-free)
constexpr int VPITCH = 136;    // V pitch  (PV B-frag conflict-free)
constexpr int PP = 68;         // P pitch
constexpr float kScale = 0.08838834764831845f;  // 1/sqrt(128)

struct Smem {
  float Qs[TQ * QP];        // tf32 Q, staged once            (33 KB)
  float KV[TK * VPITCH];    // shared K/V tile buffer         (34 KB)
  float Ps[TQ * PP];        // normalized tf32 P              (17 KB)
  float Zp[2][TQ];
  float rZs[TQ];
  float Vps[2][kD];
  float Vcsum[kD];
};
constexpr int SMEM_BYTES = (int)sizeof(Smem);   // ~86 KB -> 2 CTAs/SM

__device__ __forceinline__ uint32_t f2tf32(float f) {
  uint32_t u; asm("cvt.rna.tf32.f32 %0, %1;" : "=r"(u) : "f"(f)); return u;
}
__device__ __forceinline__ float tff(float f) { return __uint_as_float(f2tf32(f)); }

__device__ __forceinline__ void mma_tf32(float c[4], float a0, float a1,
                                         float a2, float a3, float b0, float b1) {
  asm volatile(
      "mma.sync.aligned.m16n8k8.row.col.f32.tf32.tf32.f32 "
      "{%0,%1,%2,%3}, {%4,%5,%6,%7}, {%8,%9}, {%0,%1,%2,%3};\n"
      : "+f"(c[0]), "+f"(c[1]), "+f"(c[2]), "+f"(c[3])
      : "r"(__float_as_uint(a0)), "r"(__float_as_uint(a1)),
        "r"(__float_as_uint(a2)), "r"(__float_as_uint(a3)),
        "r"(__float_as_uint(b0)), "r"(__float_as_uint(b1)));
}
}  // namespace

extern "C" __global__ void __launch_bounds__(NT, 2)
sdpa_kernel(const float* __restrict__ Q, const float* __restrict__ K,
            const float* __restrict__ V, float* __restrict__ out,
            float* __restrict__ attn)
{
  extern __shared__ char smem_raw[];
  Smem& sm = *reinterpret_cast<Smem*>(smem_raw);

  const int qt  = blockIdx.x;
  const int b   = blockIdx.y;
  const int tid = threadIdx.x;
  const int q0  = qt * TQ;
  const int wid  = tid >> 5;        // 0..7
  const int lane = tid & 31;
  const int wr   = wid >> 1;        // 0..3 (16-row band)
  const int wc   = wid & 1;         // 0..1 (32 QK cols / 64 PV cols)
  const int gid  = lane >> 2;       // 0..7
  const int tig  = lane & 3;        // 0..3
  const int r0 = 16 * wr + gid, r1 = r0 + 8;

  const float* Qb = Q + (size_t)b * kS * kD;
  const float* Kb = K + (size_t)b * kS * kD;
  const float* Vb = V + (size_t)b * kS * kD;
  float* outb  = out  + (size_t)b * kS * kD;
  float* attnb = attn + (size_t)b * kS * kS;

  // ---- stage Q once (tf32, pitch 132) ----
  {
    const float4* Qg = reinterpret_cast<const float4*>(Qb + (size_t)q0 * kD);
#pragma unroll
    for (int j = 0; j < 8; ++j) {
      const int f = tid + j * NT;
      const int r = f >> 5, c4 = f & 31;
      float4 v = Qg[f];
      float4 t = make_float4(tff(v.x), tff(v.y), tff(v.z), tff(v.w));
      *reinterpret_cast<float4*>(&sm.Qs[r * QP + c4 * 4]) = t;
    }
  }

  // ============ Pass A: Z only (no stores) ============
  float zrow0 = 0.f, zrow1 = 0.f;
  float4 kreg[8];
  {
    const float4* Kg = reinterpret_cast<const float4*>(Kb + (size_t)qt * TK * kD);
#pragma unroll
    for (int j = 0; j < 8; ++j) kreg[j] = Kg[tid + j * NT];
  }
  __syncthreads();   // Qs ready (also covers first KV write ordering)

  for (int kt = qt; kt < NKT; ++kt) {
    // stage K (tf32, pitch 132)
#pragma unroll
    for (int j = 0; j < 8; ++j) {
      const int f = tid + j * NT;
      const int r = f >> 5, c4 = f & 31;
      float4 t = make_float4(tff(kreg[j].x), tff(kreg[j].y),
                             tff(kreg[j].z), tff(kreg[j].w));
      *reinterpret_cast<float4*>(&sm.KV[r * KPITCH + c4 * 4]) = t;
    }
    __syncthreads();
    if (kt + 1 < NKT) {
      const float4* Kg = reinterpret_cast<const float4*>(Kb + (size_t)(kt + 1) * TK * kD);
#pragma unroll
      for (int j = 0; j < 8; ++j) kreg[j] = Kg[tid + j * NT];
    }

    float sacc[4][4];
#pragma unroll
    for (int j = 0; j < 4; ++j)
#pragma unroll
      for (int v = 0; v < 4; ++v) sacc[j][v] = 0.f;
    const float* Qr0 = &sm.Qs[r0 * QP];
    const float* Qr1 = &sm.Qs[r1 * QP];
#pragma unroll
    for (int s = 0; s < 16; ++s) {
      const int d = 8 * s + tig;
      const float a0 = Qr0[d], a1 = Qr1[d], a2 = Qr0[d + 4], a3 = Qr1[d + 4];
#pragma unroll
      for (int j = 0; j < 4; ++j) {
        const int c0 = (32 * wc + 8 * j + gid) * KPITCH + 8 * s + tig;
        mma_tf32(sacc[j], a0, a1, a2, a3, sm.KV[c0], sm.KV[c0 + 4]);
      }
    }
    const bool diag = (kt == qt);
#pragma unroll
    for (int j = 0; j < 4; ++j) {
      const int c = 32 * wc + 8 * j + 2 * tig;
      if (diag) {
        if (c     > r0) zrow0 += __expf(sacc[j][0] * kScale);
        if (c + 1 > r0) zrow0 += __expf(sacc[j][1] * kScale);
        if (c     > r1) zrow1 += __expf(sacc[j][2] * kScale);
        if (c + 1 > r1) zrow1 += __expf(sacc[j][3] * kScale);
      } else {
        zrow0 += __expf(sacc[j][0] * kScale) + __expf(sacc[j][1] * kScale);
        zrow1 += __expf(sacc[j][2] * kScale) + __expf(sacc[j][3] * kScale);
      }
    }
    __syncthreads();   // KV consumed; safe to overwrite
  }

  // reduce Z -> rZs
  zrow0 += __shfl_xor_sync(0xffffffffu, zrow0, 1, 4);
  zrow0 += __shfl_xor_sync(0xffffffffu, zrow0, 2, 4);
  zrow1 += __shfl_xor_sync(0xffffffffu, zrow1, 1, 4);
  zrow1 += __shfl_xor_sync(0xffffffffu, zrow1, 2, 4);
  if (tig == 0) { sm.Zp[wc][r0] = zrow0; sm.Zp[wc][r1] = zrow1; }
  __syncthreads();
  if (tid < TQ)
    sm.rZs[tid] = 1.0f / ((float)(q0 + tid + 1) + sm.Zp[0][tid] + sm.Zp[1][tid]);
  __syncthreads();

  // ============ Pass B: normalized attn + PV ============
  const float rz0 = sm.rZs[r0], rz1 = sm.rZs[r1];
  float oacc[8][4];
#pragma unroll
  for (int j = 0; j < 8; ++j)
#pragma unroll
    for (int v = 0; v < 4; ++v) oacc[j][v] = 0.f;

  {
    const float4* Kg = reinterpret_cast<const float4*>(Kb + (size_t)qt * TK * kD);
#pragma unroll
    for (int j = 0; j < 8; ++j) kreg[j] = Kg[tid + j * NT];
  }

  for (int kt = qt; kt < NKT; ++kt) {
    const int k0 = kt * TK;
    // stage K
#pragma unroll
    for (int j = 0; j < 8; ++j) {
      const int f = tid + j * NT;
      const int r = f >> 5, c4 = f & 31;
      float4 t = make_float4(tff(kreg[j].x), tff(kreg[j].y),
                             tff(kreg[j].z), tff(kreg[j].w));
      *reinterpret_cast<float4*>(&sm.KV[r * KPITCH + c4 * 4]) = t;
    }
    __syncthreads();

    // QK
    float sacc[4][4];
#pragma unroll
    for (int j = 0; j < 4; ++j)
#pragma unroll
      for (int v = 0; v < 4; ++v) sacc[j][v] = 0.f;
    const float* Qr0 = &sm.Qs[r0 * QP];
    const float* Qr1 = &sm.Qs[r1 * QP];
#pragma unroll
    for (int s = 0; s < 16; ++s) {
      const int d = 8 * s + tig;
      const float a0 = Qr0[d], a1 = Qr1[d], a2 = Qr0[d + 4], a3 = Qr1[d + 4];
#pragma unroll
      for (int j = 0; j < 4; ++j) {
        const int c0 = (32 * wc + 8 * j + gid) * KPITCH + 8 * s + tig;
        mma_tf32(sacc[j], a0, a1, a2, a3, sm.KV[c0], sm.KV[c0 + 4]);
      }
    }

    // V loads (latency covered by exp + syncs)
    float4 vreg[8];
    {
      const float4* Vg = reinterpret_cast<const float4*>(Vb + (size_t)k0 * kD);
#pragma unroll
      for (int j = 0; j < 8; ++j) vreg[j] = Vg[tid + j * NT];
    }

    // exp -> normalized attn store + Ps store
    const bool diag = (kt == qt);
    float* arow0 = attnb + (size_t)(q0 + r0) * kS + k0;
    float* arow1 = attnb + (size_t)(q0 + r1) * kS + k0;
#pragma unroll
    for (int j = 0; j < 4; ++j) {
      const int c = 32 * wc + 8 * j + 2 * tig;
      float e00, e01, e10, e11;
      if (diag) {
        e00 = (c     > r0) ? __expf(sacc[j][0] * kScale) * rz0 : rz0;
        e01 = (c + 1 > r0) ? __expf(sacc[j][1] * kScale) * rz0 : rz0;
        e10 = (c     > r1) ? __expf(sacc[j][2] * kScale) * rz1 : rz1;
        e11 = (c + 1 > r1) ? __expf(sacc[j][3] * kScale) * rz1 : rz1;
      } else {
        e00 = __expf(sacc[j][0] * kScale) * rz0;
        e01 = __expf(sacc[j][1] * kScale) * rz0;
        e10 = __expf(sacc[j][2] * kScale) * rz1;
        e11 = __expf(sacc[j][3] * kScale) * rz1;
      }
      *reinterpret_cast<float2*>(arow0 + c) = make_float2(e00, e01);
      *reinterpret_cast<float2*>(arow1 + c) = make_float2(e10, e11);
      *reinterpret_cast<float2*>(&sm.Ps[r0 * PP + c]) = make_float2(tff(e00), tff(e01));
      *reinterpret_cast<float2*>(&sm.Ps[r1 * PP + c]) = make_float2(tff(e10), tff(e11));
    }
    __syncthreads();   // all QK reads of KV done; Ps written

    // stage V into KV (tf32, pitch 136)
#pragma unroll
    for (int j = 0; j < 8; ++j) {
      const int f = tid + j * NT;
      const int r = f >> 5, c4 = f & 31;
      float4 t = make_float4(tff(vreg[j].x), tff(vreg[j].y),
                             tff(vreg[j].z), tff(vreg[j].w));
      *reinterpret_cast<float4*>(&sm.KV[r * VPITCH + c4 * 4]) = t;
    }
    __syncthreads();

    // PV: rows r0/r1, out cols 64*wc..+64
#pragma unroll
    for (int kk = 0; kk < TK; kk += 8) {
      const float a0 = sm.Ps[r0 * PP + kk + tig];
      const float a1 = sm.Ps[r1 * PP + kk + tig];
      const float a2 = sm.Ps[r0 * PP + kk + tig + 4];
      const float a3 = sm.Ps[r1 * PP + kk + tig + 4];
#pragma unroll
      for (int j = 0; j < 8; ++j) {
        const int c0 = (kk + tig) * VPITCH + 64 * wc + 8 * j + gid;
        mma_tf32(oacc[j], a0, a1, a2, a3, sm.KV[c0], sm.KV[c0 + 4 * VPITCH]);
      }
    }

    // prefetch next K (issued before loop-end sync; lands during next staging)
    if (kt + 1 < NKT) {
      const float4* Kg = reinterpret_cast<const float4*>(Kb + (size_t)(k0 + TK) * kD);
#pragma unroll
      for (int j = 0; j < 8; ++j) kreg[j] = Kg[tid + j * NT];
    }
    __syncthreads();   // PV reads done; safe to overwrite KV/Ps
  }

  // ============ Phase 2 ============
  // lower-region V column sums (deterministic, 4-way MLP)
  {
    const int vc = tid & 127, vq = tid >> 7;   // 2 groups
    float a0 = 0.f, a1 = 0.f, a2 = 0.f, a3 = 0.f;
    for (int t = vq; t < q0; t += 8) {
      a0 += Vb[(size_t)t * kD + vc];
      a1 += Vb[(size_t)(t + 2) * kD + vc];
      a2 += Vb[(size_t)(t + 4) * kD + vc];
      a3 += Vb[(size_t)(t + 6) * kD + vc];
    }
    sm.Vps[vq][vc] = (a0 + a1) + (a2 + a3);
  }

  // lower attn fill = 1/Z
  const int ftr = tid >> 4, ftc = tid & 15;   // 16 row-slots x 16 float4 cols
  for (int kt = 0; kt < qt; ++kt) {
    const int k0 = kt * TK;
#pragma unroll
    for (int p = 0; p < 4; ++p) {
      const int r = ftr + 16 * p;
      const float rz = sm.rZs[r];
      *reinterpret_cast<float4*>(&attnb[(size_t)(q0 + r) * kS + k0 + 4 * ftc]) =
          make_float4(rz, rz, rz, rz);
    }
  }
  __syncthreads();
  if (tid < kD) sm.Vcsum[tid] = sm.Vps[0][tid] + sm.Vps[1][tid];
  __syncthreads();

  // final output: oacc holds normalized PV; add rz * lower-V sum
  {
#pragma unroll
    for (int j = 0; j < 8; ++j) {
      const int c = 64 * wc + 8 * j + 2 * tig;
      const float vs0 = sm.Vcsum[c], vs1 = sm.Vcsum[c + 1];
      float2 o0 = make_float2(oacc[j][0] + rz0 * vs0, oacc[j][1] + rz0 * vs1);
      float2 o1 = make_float2(oacc[j][2] + rz1 * vs0, oacc[j][3] + rz1 * vs1);
      *reinterpret_cast<float2*>(&outb[(size_t)(q0 + r0) * kD + c]) = o0;
      *reinterpret_cast<float2*>(&outb[(size_t)(q0 + r1) * kD + c]) = o1;
    }
  }
}

extern "C" void kernel_launch(void* const* d_in, const int* in_sizes, int n_in,
                              void* d_out, int out_size) {
  (void)in_sizes; (void)n_in; (void)out_size;
  const float* Q = (const float*)d_in[0];
  const float* K = (const float*)d_in[1];
  const float* V = (const float*)d_in[2];
  float* out  = (float*)d_out;
  float* attn = out + (size_t)kB * kS * kD;

  cudaFuncSetAttribute(sdpa_kernel, cudaFuncAttributeMaxDynamicSharedMemorySize,
                       SMEM_BYTES);
  dim3 grid(NKT, kB);   // qt ascending -> heaviest first
  sdpa_kernel<<<grid, NT, SMEM_BYTES>>>(Q, K, V, out, attn);
}

// round 10
// speedup vs baseline: 1.2467x; 1.2467x over previous
#include <cuda_runtime.h>
#include <cstdint>
#include <cstddef>

namespace {
constexpr int kB = 16, kS = 2048, kD = 128, TQ = 64, TK = 64, NT = 512;
constexpr int NKT = kS / TK;   // 32
constexpr int QP = 132;        // Q pitch (floats)
constexpr int KP = 132;        // K pitch
constexpr int VTP = 68;        // V^T pitch ([d=128][tok=64])
constexpr int PP = 68;         // P pitch
constexpr float kScale = 0.08838834764831845f;  // 1/sqrt(128)

struct Smem {
  float Qs[TQ * QP];       // 33.8 KB tf32
  float Ks[TK * KP];       // 33.8 KB tf32
  float VT[kD * VTP];      // 34.8 KB tf32, transposed [d][tok]
  float Ps[TQ * PP];       // 17.4 KB tf32
  float Zs[TQ];
  float rZs[TQ];
  float Zp[4][TQ];
  float Vps[4][kD];
  float Vcsum[kD];
};
constexpr int SMEM_BYTES = (int)sizeof(Smem);

__device__ __forceinline__ uint32_t f2tf32(float f) {
  uint32_t u; asm("cvt.rna.tf32.f32 %0, %1;" : "=r"(u) : "f"(f)); return u;
}
__device__ __forceinline__ float tff(float f) { return __uint_as_float(f2tf32(f)); }

__device__ __forceinline__ void ldm_x4(uint32_t& r0, uint32_t& r1,
                                       uint32_t& r2, uint32_t& r3, uint32_t a) {
  asm volatile("ldmatrix.sync.aligned.m8n8.x4.shared.b16 {%0,%1,%2,%3}, [%4];"
               : "=r"(r0), "=r"(r1), "=r"(r2), "=r"(r3) : "r"(a));
}
__device__ __forceinline__ void mma_tf32(float c[4], uint32_t a0, uint32_t a1,
                                         uint32_t a2, uint32_t a3,
                                         uint32_t b0, uint32_t b1) {
  asm volatile(
      "mma.sync.aligned.m16n8k8.row.col.f32.tf32.tf32.f32 "
      "{%0,%1,%2,%3}, {%4,%5,%6,%7}, {%8,%9}, {%0,%1,%2,%3};\n"
      : "+f"(c[0]), "+f"(c[1]), "+f"(c[2]), "+f"(c[3])
      : "r"(a0), "r"(a1), "r"(a2), "r"(a3), "r"(b0), "r"(b1));
}
}  // namespace

extern "C" __global__ void __launch_bounds__(NT, 1)
sdpa_kernel(const float* __restrict__ Q, const float* __restrict__ K,
            const float* __restrict__ V, float* __restrict__ out,
            float* __restrict__ attn)
{
  extern __shared__ char smem_raw[];
  Smem& sm = *reinterpret_cast<Smem*>(smem_raw);

  const int qt  = blockIdx.x;
  const int b   = blockIdx.y;
  const int tid = threadIdx.x;
  const int q0  = qt * TQ;
  const int wid  = tid >> 5;        // 0..15
  const int lane = tid & 31;
  const int wr   = wid >> 2;        // 0..3 (16-row band)
  const int wc   = wid & 3;         // 0..3 (16 QK cols / 32 PV cols)
  const int gid  = lane >> 2;       // 0..7
  const int tig  = lane & 3;        // 0..3
  const int r0 = 16 * wr + gid, r1 = r0 + 8;

  const float* Qb = Q + (size_t)b * kS * kD;
  const float* Kb = K + (size_t)b * kS * kD;
  const float* Vb = V + (size_t)b * kS * kD;
  float* outb  = out  + (size_t)b * kS * kD;
  float* attnb = attn + (size_t)b * kS * kS;

  // shared-space byte addresses for ldmatrix
  const uint32_t smQ  = (uint32_t)__cvta_generic_to_shared(sm.Qs);
  const uint32_t smK  = (uint32_t)__cvta_generic_to_shared(sm.Ks);
  const uint32_t smVT = (uint32_t)__cvta_generic_to_shared(sm.VT);
  const uint32_t smP  = (uint32_t)__cvta_generic_to_shared(sm.Ps);

  // ldmatrix base addresses (per-thread)
  // A (Q or P): row = 16*wr + (lane&15), k-halfblock from lane>>4
  const uint32_t qa_base = smQ + (uint32_t)((16 * wr + (lane & 15)) * QP * 4 + (lane >> 4) * 16);
  const uint32_t pa_base = smP + (uint32_t)((16 * wr + (lane & 15)) * PP * 4 + (lane >> 4) * 16);
  // B for QK (Ks rows = tokens): row = 16*wc + (lane&7) + 8*(lane>>4), k from (lane>>3)&1
  const uint32_t kb_base = smK + (uint32_t)((16 * wc + (lane & 7) + 8 * (lane >> 4)) * KP * 4 +
                                            ((lane >> 3) & 1) * 16);
  // B for PV (VT rows = d): row = 32*wc + (lane&7) + 8*(lane>>4) (+16 per t), k from (lane>>3)&1
  const uint32_t vb_base = smVT + (uint32_t)((32 * wc + (lane & 7) + 8 * (lane >> 4)) * VTP * 4 +
                                             ((lane >> 3) & 1) * 16);

  // ---- stage Q (tf32, once) ----
  {
    const float4* Qg = reinterpret_cast<const float4*>(Qb + (size_t)q0 * kD);
#pragma unroll
    for (int j = 0; j < 4; ++j) {
      const int f = tid + j * NT;
      const int r = f >> 5;
      float4 v = Qg[f];
      float4 t = make_float4(tff(v.x), tff(v.y), tff(v.z), tff(v.w));
      *reinterpret_cast<float4*>(&sm.Qs[r * QP + lane * 4]) = t;
    }
  }
  if (tid < TQ) sm.Zs[tid] = (float)q0;

  // ---- prefetch first K/V tile into registers ----
  float4 kreg[4];
  float vreg[16];
  const int vd = 32 * (wid & 3) + lane;   // d column this thread handles
  const int vt0 = 4 * (wid >> 2);         // base token
  {
    const float4* Kg = reinterpret_cast<const float4*>(Kb + (size_t)qt * TK * kD);
#pragma unroll
    for (int j = 0; j < 4; ++j) kreg[j] = Kg[tid + j * NT];
    const float* Vg = Vb + (size_t)qt * TK * kD;
#pragma unroll
    for (int j = 0; j < 4; ++j)
#pragma unroll
      for (int t = 0; t < 4; ++t)
        vreg[4 * j + t] = Vg[(size_t)(vt0 + 16 * j + t) * kD + vd];
  }

  float oacc[4][4];
#pragma unroll
  for (int j = 0; j < 4; ++j)
#pragma unroll
    for (int v = 0; v < 4; ++v) oacc[j][v] = 0.f;

  // ================= Phase 1: upper (incl diagonal) tiles =================
  for (int kt = qt; kt < NKT; ++kt) {
    const int k0 = kt * TK;
    __syncthreads();   // prev tile's reads done; Q/Zs ready on i=0

    // ---- stage K (tf32) ----
#pragma unroll
    for (int j = 0; j < 4; ++j) {
      const int f = tid + j * NT;
      const int r = f >> 5;
      float4 t = make_float4(tff(kreg[j].x), tff(kreg[j].y),
                             tff(kreg[j].z), tff(kreg[j].w));
      *reinterpret_cast<float4*>(&sm.Ks[r * KP + lane * 4]) = t;
    }
    // ---- stage V transposed (tf32): VT[d][tok] ----
#pragma unroll
    for (int j = 0; j < 4; ++j) {
      float4 t = make_float4(tff(vreg[4 * j + 0]), tff(vreg[4 * j + 1]),
                             tff(vreg[4 * j + 2]), tff(vreg[4 * j + 3]));
      *reinterpret_cast<float4*>(&sm.VT[vd * VTP + vt0 + 16 * j]) = t;
    }
    // prefetch next tile
    if (kt + 1 < NKT) {
      const float4* Kg = reinterpret_cast<const float4*>(Kb + (size_t)(k0 + TK) * kD);
#pragma unroll
      for (int j = 0; j < 4; ++j) kreg[j] = Kg[tid + j * NT];
      const float* Vg = Vb + (size_t)(k0 + TK) * kD;
#pragma unroll
      for (int j = 0; j < 4; ++j)
#pragma unroll
        for (int t = 0; t < 4; ++t)
          vreg[4 * j + t] = Vg[(size_t)(vt0 + 16 * j + t) * kD + vd];
    }
    __syncthreads();   // Ks/VT visible

    // ---- QK^T: rows 16wr..+16, cols 16wc..+16 ----
    float sacc[2][4];
#pragma unroll
    for (int j = 0; j < 2; ++j)
#pragma unroll
      for (int v = 0; v < 4; ++v) sacc[j][v] = 0.f;
#pragma unroll
    for (int s = 0; s < 16; ++s) {
      uint32_t a0, a1, a2, a3, b0, b1, b2, b3;
      ldm_x4(a0, a1, a2, a3, qa_base + (uint32_t)(s * 32));
      ldm_x4(b0, b1, b2, b3, kb_base + (uint32_t)(s * 32));
      mma_tf32(sacc[0], a0, a1, a2, a3, b0, b1);
      mma_tf32(sacc[1], a0, a1, a2, a3, b2, b3);
    }

    // ---- mask + exp; attn store; Ps store (tf32); Z partials ----
    const bool diag = (kt == qt);
    float rs0 = 0.f, rs1 = 0.f;
    float* arow0 = attnb + (size_t)(q0 + r0) * kS + k0;
    float* arow1 = attnb + (size_t)(q0 + r1) * kS + k0;
#pragma unroll
    for (int j = 0; j < 2; ++j) {
      const int c = 16 * wc + 8 * j + 2 * tig;
      float e00, e01, e10, e11;
      if (diag) {
        e00 = (c     > r0) ? __expf(sacc[j][0] * kScale) : 1.0f;
        e01 = (c + 1 > r0) ? __expf(sacc[j][1] * kScale) : 1.0f;
        e10 = (c     > r1) ? __expf(sacc[j][2] * kScale) : 1.0f;
        e11 = (c + 1 > r1) ? __expf(sacc[j][3] * kScale) : 1.0f;
      } else {
        e00 = __expf(sacc[j][0] * kScale);
        e01 = __expf(sacc[j][1] * kScale);
        e10 = __expf(sacc[j][2] * kScale);
        e11 = __expf(sacc[j][3] * kScale);
      }
      rs0 += e00 + e01;
      rs1 += e10 + e11;
      *reinterpret_cast<float2*>(arow0 + c) = make_float2(e00, e01);
      *reinterpret_cast<float2*>(arow1 + c) = make_float2(e10, e11);
      *reinterpret_cast<float2*>(&sm.Ps[r0 * PP + c]) = make_float2(tff(e00), tff(e01));
      *reinterpret_cast<float2*>(&sm.Ps[r1 * PP + c]) = make_float2(tff(e10), tff(e11));
    }
    rs0 += __shfl_xor_sync(0xffffffffu, rs0, 1, 4);
    rs0 += __shfl_xor_sync(0xffffffffu, rs0, 2, 4);
    rs1 += __shfl_xor_sync(0xffffffffu, rs1, 1, 4);
    rs1 += __shfl_xor_sync(0xffffffffu, rs1, 2, 4);
    if (tig == 0) { sm.Zp[wc][r0] = rs0; sm.Zp[wc][r1] = rs1; }
    __syncthreads();   // Ps + Zp visible
    if (tid < TQ)
      sm.Zs[tid] += (sm.Zp[0][tid] + sm.Zp[1][tid]) +
                    (sm.Zp[2][tid] + sm.Zp[3][tid]);

    // ---- PV: rows 16wr..+16, out cols 32wc..+32 ----
#pragma unroll
    for (int kk = 0; kk < 8; ++kk) {
      uint32_t a0, a1, a2, a3;
      ldm_x4(a0, a1, a2, a3, pa_base + (uint32_t)(kk * 32));
#pragma unroll
      for (int t = 0; t < 2; ++t) {
        uint32_t b0, b1, b2, b3;
        ldm_x4(b0, b1, b2, b3,
               vb_base + (uint32_t)(t * 16 * VTP * 4 + kk * 32));
        mma_tf32(oacc[2 * t + 0], a0, a1, a2, a3, b0, b1);
        mma_tf32(oacc[2 * t + 1], a0, a1, a2, a3, b2, b3);
      }
    }
  }

  // ================= Phase 2 =================
  __syncthreads();
  if (tid < TQ) sm.rZs[tid] = 1.0f / sm.Zs[tid];
  __syncthreads();

  // lower-region V column sums (deterministic, 4-way MLP)
  {
    const int vc = tid & 127, vq = tid >> 7;
    float a0 = 0.f, a1 = 0.f, a2 = 0.f, a3 = 0.f;
    for (int t = vq; t < q0; t += 16) {
      a0 += Vb[(size_t)t * kD + vc];
      a1 += Vb[(size_t)(t + 4) * kD + vc];
      a2 += Vb[(size_t)(t + 8) * kD + vc];
      a3 += Vb[(size_t)(t + 12) * kD + vc];
    }
    sm.Vps[vq][vc] = (a0 + a1) + (a2 + a3);
  }

  // lower attn fill = 1/Z
  const int ftr = tid >> 4, ftc = tid & 15;   // 32 row-slots x 16 float4 cols
  for (int kt = 0; kt < qt; ++kt) {
    const int k0 = kt * TK;
#pragma unroll
    for (int p = 0; p < 2; ++p) {
      const int r = ftr + 32 * p;
      const float rz = sm.rZs[r];
      *reinterpret_cast<float4*>(&attnb[(size_t)(q0 + r) * kS + k0 + 4 * ftc]) =
          make_float4(rz, rz, rz, rz);
    }
  }
  __syncthreads();
  if (tid < kD)
    sm.Vcsum[tid] = (sm.Vps[0][tid] + sm.Vps[1][tid]) +
                    (sm.Vps[2][tid] + sm.Vps[3][tid]);
  __syncthreads();

  // rescale upper attn tiles (2 k-tiles in flight for MLP)
  {
    const float rzA = sm.rZs[ftr];
    const float rzB = sm.rZs[ftr + 32];
    int kt = qt;
    for (; kt + 1 < NKT; kt += 2) {
      float4* p00 = reinterpret_cast<float4*>(&attnb[(size_t)(q0 + ftr) * kS + kt * TK + 4 * ftc]);
      float4* p01 = reinterpret_cast<float4*>(&attnb[(size_t)(q0 + ftr + 32) * kS + kt * TK + 4 * ftc]);
      float4* p10 = reinterpret_cast<float4*>(&attnb[(size_t)(q0 + ftr) * kS + (kt + 1) * TK + 4 * ftc]);
      float4* p11 = reinterpret_cast<float4*>(&attnb[(size_t)(q0 + ftr + 32) * kS + (kt + 1) * TK + 4 * ftc]);
      float4 v00 = *p00, v01 = *p01, v10 = *p10, v11 = *p11;
      v00.x *= rzA; v00.y *= rzA; v00.z *= rzA; v00.w *= rzA;
      v01.x *= rzB; v01.y *= rzB; v01.z *= rzB; v01.w *= rzB;
      v10.x *= rzA; v10.y *= rzA; v10.z *= rzA; v10.w *= rzA;
      v11.x *= rzB; v11.y *= rzB; v11.z *= rzB; v11.w *= rzB;
      *p00 = v00; *p01 = v01; *p10 = v10; *p11 = v11;
    }
    if (kt < NKT) {
      float4* p00 = reinterpret_cast<float4*>(&attnb[(size_t)(q0 + ftr) * kS + kt * TK + 4 * ftc]);
      float4* p01 = reinterpret_cast<float4*>(&attnb[(size_t)(q0 + ftr + 32) * kS + kt * TK + 4 * ftc]);
      float4 v00 = *p00, v01 = *p01;
      v00.x *= rzA; v00.y *= rzA; v00.z *= rzA; v00.w *= rzA;
      v01.x *= rzB; v01.y *= rzB; v01.z *= rzB; v01.w *= rzB;
      *p00 = v00; *p01 = v01;
    }
  }

  // final output
  {
    const float rz0 = sm.rZs[r0], rz1 = sm.rZs[r1];
#pragma unroll
    for (int j = 0; j < 4; ++j) {
      const int c = 32 * wc + 8 * j + 2 * tig;
      const float vs0 = sm.Vcsum[c], vs1 = sm.Vcsum[c + 1];
      float2 o0 = make_float2(rz0 * (oacc[j][0] + vs0), rz0 * (oacc[j][1] + vs1));
      float2 o1 = make_float2(rz1 * (oacc[j][2] + vs0), rz1 * (oacc[j][3] + vs1));
      *reinterpret_cast<float2*>(&outb[(size_t)(q0 + r0) * kD + c]) = o0;
      *reinterpret_cast<float2*>(&outb[(size_t)(q0 + r1) * kD + c]) = o1;
    }
  }
}

extern "C" void kernel_launch(void* const* d_in, const int* in_sizes, int n_in,
                              void* d_out, int out_size) {
  (void)in_sizes; (void)n_in; (void)out_size;
  const float* Q = (const float*)d_in[0];
  const float* K = (const float*)d_in[1];
  const float* V = (const float*)d_in[2];
  float* out  = (float*)d_out;
  float* attn = out + (size_t)kB * kS * kD;

  cudaFuncSetAttribute(sdpa_kernel, cudaFuncAttributeMaxDynamicSharedMemorySize,
                       SMEM_BYTES);
  dim3 grid(NKT, kB);
  sdpa_kernel<<<grid, NT, SMEM_BYTES>>>(Q, K, V, out, attn);
}